// round 13
// baseline (speedup 1.0000x reference)
#include <cuda_runtime.h>
#include <cuda_fp16.h>
#include <math.h>
#include <stdint.h>

#define DIM 128

// ---------------------------------------------------------------------------
// device scratch (allocation-free: __device__ globals)
// ---------------------------------------------------------------------------
__device__ float    g_row_loss[4096];
__device__ float2   g_part[2048 * 800];    // per-(row, half-tile) (max, sumexp)
__device__ __half   g_b16[51200 * 128];    // added_weights fp16
__device__ __half   g_x16[2048 * 128];     // x fp16

// ---------------------------------------------------------------------------
// helpers
// ---------------------------------------------------------------------------
__device__ __forceinline__ uint32_t smem_u32(const void* p) {
    uint32_t a;
    asm("{ .reg .u64 t; cvta.to.shared.u64 t, %1; cvt.u32.u64 %0, t; }" : "=r"(a) : "l"(p));
    return a;
}

#define LDMX4(r0, r1, r2, r3, addr) \
    asm volatile("ldmatrix.sync.aligned.m8n8.x4.shared.b16 {%0,%1,%2,%3}, [%4];" \
                 : "=r"(r0), "=r"(r1), "=r"(r2), "=r"(r3) : "r"(addr))

#define MMA16816F16(c0, c1, c2, c3, a0, a1, a2, a3, b0, b1) \
    asm volatile("mma.sync.aligned.m16n8k16.row.col.f32.f16.f16.f32 " \
                 "{%0,%1,%2,%3}, {%4,%5,%6,%7}, {%8,%9}, {%0,%1,%2,%3};" \
                 : "+f"(c0), "+f"(c1), "+f"(c2), "+f"(c3) \
                 : "r"(a0), "r"(a1), "r"(a2), "r"(a3), "r"(b0), "r"(b1))

#define CPASYNC16(saddr, gptr) \
    asm volatile("cp.async.cg.shared.global [%0], [%1], 16;" :: "r"(saddr), "l"(gptr))
#define CPCOMMIT() asm volatile("cp.async.commit_group;" ::: "memory")
#define CPWAIT0()  asm volatile("cp.async.wait_group 0;" ::: "memory")

// int64-LE detection: values < 2^16 => odd 32-bit words all zero
__device__ __forceinline__ int detect64(const unsigned int* __restrict__ w) {
    int is64 = 1;
    #pragma unroll
    for (int j = 0; j < 32; ++j)
        if (w[2 * j + 1] != 0u) { is64 = 0; break; }
    return is64;
}

// ---------------------------------------------------------------------------
// launch 0: fused aw (fp32 exact out + fp16) + xconv (fp16)
// gather loop unrolled x4 with independent accumulators (MLP ~4)
// ---------------------------------------------------------------------------
__global__ void awx_kernel(const float* __restrict__ weights,
                           const int* __restrict__ path_len,
                           const void* __restrict__ pi_raw,
                           const float* __restrict__ x,
                           float* __restrict__ aw,
                           int K, int B, int Dmax, int Kpad) {
    int blk = blockIdx.x;
    int d = threadIdx.x;
    if (blk < Kpad) {
        int k = blk;
        if (k >= K) {
            g_b16[(size_t)k * DIM + d] = __float2half(0.0f);
            return;
        }
        const int is64 = detect64((const unsigned int*)pi_raw);
        int len = path_len[k];
        float s0 = weights[(size_t)k * DIM + d];
        float s1 = 0.0f, s2 = 0.0f, s3 = 0.0f;
        if (is64) {
            const long long* pp = (const long long*)pi_raw + (size_t)k * Dmax;
            int p = 0;
            for (; p + 4 <= len; p += 4) {
                int i0 = (int)pp[p],     i1 = (int)pp[p + 1];
                int i2 = (int)pp[p + 2], i3 = (int)pp[p + 3];
                s0 += weights[(size_t)i0 * DIM + d];
                s1 += weights[(size_t)i1 * DIM + d];
                s2 += weights[(size_t)i2 * DIM + d];
                s3 += weights[(size_t)i3 * DIM + d];
            }
            for (; p < len; ++p)
                s0 += weights[(size_t)((int)pp[p]) * DIM + d];
        } else {
            const int* pp = (const int*)pi_raw + (size_t)k * Dmax;
            int p = 0;
            for (; p + 4 <= len; p += 4) {
                int i0 = pp[p],     i1 = pp[p + 1];
                int i2 = pp[p + 2], i3 = pp[p + 3];
                s0 += weights[(size_t)i0 * DIM + d];
                s1 += weights[(size_t)i1 * DIM + d];
                s2 += weights[(size_t)i2 * DIM + d];
                s3 += weights[(size_t)i3 * DIM + d];
            }
            for (; p < len; ++p)
                s0 += weights[(size_t)pp[p] * DIM + d];
        }
        float s = (s0 + s1) + (s2 + s3);
        aw[(size_t)k * DIM + d] = s;
        g_b16[(size_t)k * DIM + d] = __float2half(s);
    } else {
        int r = blk - Kpad;
        float v = (r < B) ? x[(size_t)r * DIM + d] : 0.0f;
        g_x16[(size_t)r * DIM + d] = __float2half(v);
    }
}

// ---------------------------------------------------------------------------
// launch 1: fp16 HMMA GEMM, one-shot CTA per (n,m) tile; smem-staged stores;
// fused per-(row, 64-col half-tile) softmax partials (max, sumexp) -> g_part.
// grid=(ntiles, mtiles); CTA tile 128M x 128N; 8 warps 4(M)x2(N) => warp 32x64.
// ---------------------------------------------------------------------------
#define ROWB 272
#define SZ_T (128 * ROWB)
#define OFF_A 0
#define OFF_B (SZ_T)
#define SMEM_TOTAL (2 * SZ_T)
#define STG_ROWW 132

__global__ void __launch_bounds__(256, 2)
gemm_kernel(float* __restrict__ logits, int B, int K) {
    extern __shared__ char smem[];
    const uint32_t sb = smem_u32(smem);
    const int tid  = threadIdx.x;
    const int lane = tid & 31;
    const int wid  = tid >> 5;
    const int wm   = wid >> 1;          // 0..3  (32-row band)
    const int wn   = wid & 1;           // 0..1  (64-col band)
    const int nbase = blockIdx.x * 128;
    const int m     = blockIdx.y;
    const int P     = 2 * gridDim.x;    // partials per row

    // B tile: 128 rows fp16
    {
        const char* sBp = (const char*)(g_b16 + (size_t)nbase * DIM);
        #pragma unroll
        for (int i = 0; i < 8; ++i) {
            int idx = tid + i * 256;
            int row = idx >> 4, q = idx & 15;
            CPASYNC16(sb + OFF_B + row * ROWB + q * 16, sBp + idx * 16);
        }
    }
    // A tile: 128 rows fp16
    {
        const char* sAp = (const char*)(g_x16 + (size_t)m * 128 * DIM);
        #pragma unroll
        for (int i = 0; i < 8; ++i) {
            int idx = tid + i * 256;
            int row = idx >> 4, q = idx & 15;
            CPASYNC16(sb + OFF_A + row * ROWB + q * 16, sAp + idx * 16);
        }
    }
    CPCOMMIT();
    CPWAIT0();
    __syncthreads();

    const uint32_t a_row  = (uint32_t)(wm * 32 + (lane & 15));
    const uint32_t a_kh   = (uint32_t)((lane >> 4) * 8);
    const uint32_t b_row0 = (uint32_t)(wn * 64 + ((lane >> 4) & 1) * 8 + (lane & 7));
    const uint32_t b_kh   = (uint32_t)(((lane >> 3) & 1) * 8);

    float acc[2][8][4];
    #pragma unroll
    for (int i = 0; i < 2; ++i)
        #pragma unroll
        for (int j = 0; j < 8; ++j)
            #pragma unroll
            for (int e = 0; e < 4; ++e) acc[i][j][e] = 0.0f;

    #pragma unroll
    for (int ks = 0; ks < 8; ++ks) {
        const uint32_t koff = (ks * 16) * 2;
        uint32_t af[2][4];
        #pragma unroll
        for (int mt = 0; mt < 2; ++mt) {
            uint32_t ra = (a_row + mt * 16) * ROWB + koff + a_kh * 2;
            LDMX4(af[mt][0], af[mt][1], af[mt][2], af[mt][3], sb + OFF_A + ra);
        }
        uint32_t bf[8][2];
        #pragma unroll
        for (int q = 0; q < 4; ++q) {
            uint32_t rb = (b_row0 + q * 16) * ROWB + koff + b_kh * 2;
            uint32_t r0, r1, r2, r3;
            LDMX4(r0, r1, r2, r3, sb + OFF_B + rb);
            bf[2 * q][0] = r0;     bf[2 * q][1] = r1;
            bf[2 * q + 1][0] = r2; bf[2 * q + 1][1] = r3;
        }
        #pragma unroll
        for (int mt = 0; mt < 2; ++mt)
            #pragma unroll
            for (int nt = 0; nt < 8; ++nt)
                MMA16816F16(acc[mt][nt][0], acc[mt][nt][1], acc[mt][nt][2], acc[mt][nt][3],
                            af[mt][0], af[mt][1], af[mt][2], af[mt][3],
                            bf[nt][0], bf[nt][1]);
    }

    // ---- epilogue: stage to smem + per-row softmax partials ----
    __syncthreads();
    float* stage = (float*)smem;

    #pragma unroll
    for (int mt = 0; mt < 2; ++mt) {
        #pragma unroll
        for (int h = 0; h < 2; ++h) {
            int rloc = wm * 32 + mt * 16 + h * 8 + (lane >> 2);
            float v[16];
            float rmax = -1e30f;
            #pragma unroll
            for (int nt = 0; nt < 8; ++nt) {
                int cloc = wn * 64 + (lane & 3) * 2 + nt * 8;
                float v0 = acc[mt][nt][2 * h];
                float v1 = acc[mt][nt][2 * h + 1];
                *(float2*)&stage[rloc * STG_ROWW + cloc] = make_float2(v0, v1);
                int n = nbase + cloc;
                v[2 * nt]     = (n < K)     ? v0 : -1e30f;
                v[2 * nt + 1] = (n + 1 < K) ? v1 : -1e30f;
                rmax = fmaxf(rmax, fmaxf(v[2 * nt], v[2 * nt + 1]));
            }
            rmax = fmaxf(rmax, __shfl_xor_sync(0xFFFFFFFFu, rmax, 1));
            rmax = fmaxf(rmax, __shfl_xor_sync(0xFFFFFFFFu, rmax, 2));
            float s = 0.0f;
            #pragma unroll
            for (int e = 0; e < 16; ++e) s += __expf(v[e] - rmax);
            s += __shfl_xor_sync(0xFFFFFFFFu, s, 1);
            s += __shfl_xor_sync(0xFFFFFFFFu, s, 2);
            int gr = m * 128 + rloc;
            if ((lane & 3) == 0 && gr < B)
                g_part[(size_t)gr * P + 2 * blockIdx.x + wn] = make_float2(rmax, s);
        }
    }
    __syncthreads();

    // coalesced copy: 256 threads, col fixed per thread, 2 rows per iter
    {
        const int col   = tid & 127;
        const int n     = nbase + col;
        const int rloc0 = tid >> 7;
        if (n < K) {
            const float* sp = stage + rloc0 * STG_ROWW + col;
            int gr = m * 128 + rloc0;
            float* gp = logits + (size_t)gr * K + n;
            #pragma unroll 8
            for (int i = 0; i < 64; ++i) {
                if (gr < B) *gp = *sp;
                sp += 2 * STG_ROWW;
                gp += 2 * (size_t)K;
                gr += 2;
            }
        }
    }
}

// ---------------------------------------------------------------------------
// launch 2: merge partials -> row loss (float4 reads of (m,s) pairs)
// ---------------------------------------------------------------------------
__global__ void lse_kernel(const float* __restrict__ logits,
                           const void* __restrict__ y_raw,
                           int B, int K, int P) {
    int b = blockIdx.x;
    if (b >= B) return;
    int tid = threadIdx.x;
    __shared__ float sm[256];
    const float4* part4 = (const float4*)(g_part + (size_t)b * P);
    const int P2 = P >> 1;

    float m = -1e30f;
    for (int i = tid; i < P2; i += 256) {
        float4 q = part4[i];
        m = fmaxf(m, fmaxf(q.x, q.z));
    }
    if (P & 1) {
        // odd tail (P always even here: P = 2*ntiles) — kept for safety
        if (tid == 0) m = fmaxf(m, g_part[(size_t)b * P + P - 1].x);
    }
    sm[tid] = m;
    __syncthreads();
    for (int k = 128; k > 0; k >>= 1) {
        if (tid < k) sm[tid] = fmaxf(sm[tid], sm[tid + k]);
        __syncthreads();
    }
    m = sm[0];
    __syncthreads();

    float s = 0.0f;
    for (int i = tid; i < P2; i += 256) {
        float4 q = part4[i];
        s += q.y * __expf(q.x - m) + q.w * __expf(q.z - m);
    }
    sm[tid] = s;
    __syncthreads();
    for (int k = 128; k > 0; k >>= 1) {
        if (tid < k) sm[tid] += sm[tid + k];
        __syncthreads();
    }
    if (tid == 0) {
        const int is64 = detect64((const unsigned int*)y_raw);
        int yb = is64 ? (int)((const long long*)y_raw)[b]
                      : ((const int*)y_raw)[b];
        float lse = m + logf(sm[0]);
        g_row_loss[b] = lse - logits[(size_t)b * K + yb];
    }
}

// launch 3: mean
__global__ void loss_kernel(float* __restrict__ out, int B) {
    __shared__ float sm[256];
    int tid = threadIdx.x;
    float s = 0.0f;
    for (int i = tid; i < B; i += 256) s += g_row_loss[i];
    sm[tid] = s;
    __syncthreads();
    for (int k = 128; k > 0; k >>= 1) {
        if (tid < k) sm[tid] += sm[tid + k];
        __syncthreads();
    }
    if (tid == 0) out[0] = sm[0] / (float)B;
}

// ---------------------------------------------------------------------------
// launch — inputs identified by element count
// ---------------------------------------------------------------------------
extern "C" void kernel_launch(void* const* d_in, const int* in_sizes, int n_in,
                              void* d_out, int out_size) {
    int order[16];
    for (int i = 0; i < n_in; ++i) order[i] = i;
    for (int i = 0; i < n_in; ++i)
        for (int j = i + 1; j < n_in; ++j)
            if (in_sizes[order[j]] > in_sizes[order[i]]) {
                int t = order[i]; order[i] = order[j]; order[j] = t;
            }
    const float* weights  = (const float*)d_in[order[0]];
    const void*  pi_p     = d_in[order[1]];
    const float* x        = (const float*)d_in[order[2]];
    const int*   path_len = (const int*)d_in[order[3]];
    const void*  y_p      = d_in[order[4]];

    const int pi_n = in_sizes[order[1]];
    const int K    = in_sizes[order[3]];
    const int B    = in_sizes[order[4]];
    const int Dmax = pi_n / K;

    const int ntiles = (K + 127) / 128;
    const int mtiles = (B + 127) / 128;
    const int Kpad   = ntiles * 128;
    const int Mpad   = mtiles * 128;
    const int P      = 2 * ntiles;

    float* out    = (float*)d_out;
    float* loss   = out;
    float* logits = out + 1;
    float* aw     = out + 1 + (size_t)B * K;

    cudaFuncSetAttribute(gemm_kernel, cudaFuncAttributeMaxDynamicSharedMemorySize, SMEM_TOTAL);

    awx_kernel<<<Kpad + Mpad, 128>>>(weights, path_len, pi_p, x, aw, K, B, Dmax, Kpad);

    dim3 grid(ntiles, mtiles);
    gemm_kernel<<<grid, 256, SMEM_TOTAL>>>(logits, B, K);

    lse_kernel<<<B, 256>>>(logits, y_p, B, K, P);
    loss_kernel<<<1, 256>>>(loss, B);
}

// round 14
// speedup vs baseline: 1.1432x; 1.1432x over previous
#include <cuda_runtime.h>
#include <cuda_fp16.h>
#include <math.h>
#include <stdint.h>

#define DIM 128

// ---------------------------------------------------------------------------
// device scratch (allocation-free: __device__ globals)
// ---------------------------------------------------------------------------
__device__ int      g_is64;
__device__ float2   g_part[2048 * 800];    // per-(row, half-tile) (max, sumexp)
__device__ __half   g_b16[51200 * 128];    // added_weights fp16
__device__ __half   g_x16[2048 * 128];     // x fp16

// ---------------------------------------------------------------------------
// helpers
// ---------------------------------------------------------------------------
__device__ __forceinline__ uint32_t smem_u32(const void* p) {
    uint32_t a;
    asm("{ .reg .u64 t; cvta.to.shared.u64 t, %1; cvt.u32.u64 %0, t; }" : "=r"(a) : "l"(p));
    return a;
}

#define LDMX4(r0, r1, r2, r3, addr) \
    asm volatile("ldmatrix.sync.aligned.m8n8.x4.shared.b16 {%0,%1,%2,%3}, [%4];" \
                 : "=r"(r0), "=r"(r1), "=r"(r2), "=r"(r3) : "r"(addr))

#define MMA16816F16(c0, c1, c2, c3, a0, a1, a2, a3, b0, b1) \
    asm volatile("mma.sync.aligned.m16n8k16.row.col.f32.f16.f16.f32 " \
                 "{%0,%1,%2,%3}, {%4,%5,%6,%7}, {%8,%9}, {%0,%1,%2,%3};" \
                 : "+f"(c0), "+f"(c1), "+f"(c2), "+f"(c3) \
                 : "r"(a0), "r"(a1), "r"(a2), "r"(a3), "r"(b0), "r"(b1))

#define CPASYNC16(saddr, gptr) \
    asm volatile("cp.async.cg.shared.global [%0], [%1], 16;" :: "r"(saddr), "l"(gptr))
#define CPCOMMIT() asm volatile("cp.async.commit_group;" ::: "memory")
#define CPWAIT1()  asm volatile("cp.async.wait_group 1;" ::: "memory")
#define CPWAIT0()  asm volatile("cp.async.wait_group 0;" ::: "memory")

// ---------------------------------------------------------------------------
// launch 0: dtype detect + loss accumulator init
// ---------------------------------------------------------------------------
__global__ void detect_kernel(const unsigned int* __restrict__ w,
                              float* __restrict__ loss) {
    if (threadIdx.x == 0) {
        int is64 = 1;
        #pragma unroll
        for (int j = 0; j < 32; ++j)
            if (w[2 * j + 1] != 0u) { is64 = 0; break; }
        g_is64 = is64;
        *loss = 0.0f;
    }
}

// ---------------------------------------------------------------------------
// launch 1: fused aw (fp32 exact out + fp16) + xconv (fp16) [R12-exact form]
// ---------------------------------------------------------------------------
__global__ void awx_kernel(const float* __restrict__ weights,
                           const int* __restrict__ path_len,
                           const void* __restrict__ pi_raw,
                           const float* __restrict__ x,
                           float* __restrict__ aw,
                           int K, int B, int Dmax, int Kpad) {
    int blk = blockIdx.x;
    int d = threadIdx.x;
    const int is64 = g_is64;
    if (blk < Kpad) {
        int k = blk;
        float s = 0.0f;
        if (k < K) {
            s = weights[(size_t)k * DIM + d];
            int len = path_len[k];
            for (int p = 0; p < len; ++p) {
                int idx = is64 ? (int)((const long long*)pi_raw)[(size_t)k * Dmax + p]
                               : ((const int*)pi_raw)[(size_t)k * Dmax + p];
                s += weights[(size_t)idx * DIM + d];
            }
            aw[(size_t)k * DIM + d] = s;
        }
        g_b16[(size_t)k * DIM + d] = __float2half(s);
    } else {
        int r = blk - Kpad;
        float v = (r < B) ? x[(size_t)r * DIM + d] : 0.0f;
        g_x16[(size_t)r * DIM + d] = __float2half(v);
    }
}

// ---------------------------------------------------------------------------
// launch 2: fp16 HMMA GEMM, 2-stage k-pipelined loads; smem-staged stores;
// fused per-(row, 64-col half-tile) softmax partials -> g_part.
// grid=(ntiles, mtiles); CTA tile 128M x 128N; 8 warps 4(M)x2(N).
// ---------------------------------------------------------------------------
#define ROWB 272
#define SZ_T (128 * ROWB)
#define OFF_A 0
#define OFF_B (SZ_T)
#define SMEM_TOTAL (2 * SZ_T)
#define STG_ROWW 132

__global__ void __launch_bounds__(256, 2)
gemm_kernel(float* __restrict__ logits, float* __restrict__ dummy, int B, int K) {
    extern __shared__ char smem[];
    const uint32_t sb = smem_u32(smem);
    const int tid  = threadIdx.x;
    const int lane = tid & 31;
    const int wid  = tid >> 5;
    const int wm   = wid >> 1;          // 0..3  (32-row band)
    const int wn   = wid & 1;           // 0..1  (64-col band)
    const int nbase = blockIdx.x * 128;
    const int m     = blockIdx.y;
    const int P     = 2 * gridDim.x;    // partials per row

    const char* sBp = (const char*)(g_b16 + (size_t)nbase * DIM);
    const char* sAp = (const char*)(g_x16 + (size_t)m * 128 * DIM);

    // stage 0: K bytes [0,128) of each row (ks 0..3)
    #pragma unroll
    for (int i = 0; i < 4; ++i) {
        int idx = tid + i * 256;        // 0..1023
        int row = idx >> 3, q = idx & 7;
        CPASYNC16(sb + OFF_B + row * ROWB + q * 16, sBp + row * 256 + q * 16);
        CPASYNC16(sb + OFF_A + row * ROWB + q * 16, sAp + row * 256 + q * 16);
    }
    CPCOMMIT();
    // stage 1: K bytes [128,256) (ks 4..7)
    #pragma unroll
    for (int i = 0; i < 4; ++i) {
        int idx = tid + i * 256;
        int row = idx >> 3, q = (idx & 7) + 8;
        CPASYNC16(sb + OFF_B + row * ROWB + q * 16, sBp + row * 256 + q * 16);
        CPASYNC16(sb + OFF_A + row * ROWB + q * 16, sAp + row * 256 + q * 16);
    }
    CPCOMMIT();

    const uint32_t a_row  = (uint32_t)(wm * 32 + (lane & 15));
    const uint32_t a_kh   = (uint32_t)((lane >> 4) * 8);
    const uint32_t b_row0 = (uint32_t)(wn * 64 + ((lane >> 4) & 1) * 8 + (lane & 7));
    const uint32_t b_kh   = (uint32_t)(((lane >> 3) & 1) * 8);

    float acc[2][8][4];
    #pragma unroll
    for (int i = 0; i < 2; ++i)
        #pragma unroll
        for (int j = 0; j < 8; ++j)
            #pragma unroll
            for (int e = 0; e < 4; ++e) acc[i][j][e] = 0.0f;

    CPWAIT1();
    __syncthreads();

    #pragma unroll
    for (int ks = 0; ks < 8; ++ks) {
        if (ks == 4) {
            CPWAIT0();
            __syncthreads();
        }
        const uint32_t koff = (ks * 16) * 2;
        uint32_t af[2][4];
        #pragma unroll
        for (int mt = 0; mt < 2; ++mt) {
            uint32_t ra = (a_row + mt * 16) * ROWB + koff + a_kh * 2;
            LDMX4(af[mt][0], af[mt][1], af[mt][2], af[mt][3], sb + OFF_A + ra);
        }
        uint32_t bf[8][2];
        #pragma unroll
        for (int q = 0; q < 4; ++q) {
            uint32_t rb = (b_row0 + q * 16) * ROWB + koff + b_kh * 2;
            uint32_t r0, r1, r2, r3;
            LDMX4(r0, r1, r2, r3, sb + OFF_B + rb);
            bf[2 * q][0] = r0;     bf[2 * q][1] = r1;
            bf[2 * q + 1][0] = r2; bf[2 * q + 1][1] = r3;
        }
        #pragma unroll
        for (int mt = 0; mt < 2; ++mt)
            #pragma unroll
            for (int nt = 0; nt < 8; ++nt)
                MMA16816F16(acc[mt][nt][0], acc[mt][nt][1], acc[mt][nt][2], acc[mt][nt][3],
                            af[mt][0], af[mt][1], af[mt][2], af[mt][3],
                            bf[nt][0], bf[nt][1]);
    }

    // ---- epilogue: stage to smem + per-row softmax partials ----
    __syncthreads();
    float* stage = (float*)smem;

    #pragma unroll
    for (int mt = 0; mt < 2; ++mt) {
        #pragma unroll
        for (int h = 0; h < 2; ++h) {
            int rloc = wm * 32 + mt * 16 + h * 8 + (lane >> 2);
            float v[16];
            float rmax = -1e30f;
            #pragma unroll
            for (int nt = 0; nt < 8; ++nt) {
                int cloc = wn * 64 + (lane & 3) * 2 + nt * 8;
                float v0 = acc[mt][nt][2 * h];
                float v1 = acc[mt][nt][2 * h + 1];
                *(float2*)&stage[rloc * STG_ROWW + cloc] = make_float2(v0, v1);
                int n = nbase + cloc;
                v[2 * nt]     = (n < K)     ? v0 : -1e30f;
                v[2 * nt + 1] = (n + 1 < K) ? v1 : -1e30f;
                rmax = fmaxf(rmax, fmaxf(v[2 * nt], v[2 * nt + 1]));
            }
            rmax = fmaxf(rmax, __shfl_xor_sync(0xFFFFFFFFu, rmax, 1));
            rmax = fmaxf(rmax, __shfl_xor_sync(0xFFFFFFFFu, rmax, 2));
            float s = 0.0f;
            #pragma unroll
            for (int e = 0; e < 16; ++e) s += __expf(v[e] - rmax);
            s += __shfl_xor_sync(0xFFFFFFFFu, s, 1);
            s += __shfl_xor_sync(0xFFFFFFFFu, s, 2);
            int gr = m * 128 + rloc;
            if ((lane & 3) == 0 && gr < B)
                g_part[(size_t)gr * P + 2 * blockIdx.x + wn] = make_float2(rmax, s);
        }
    }
    __syncthreads();

    // coalesced copy: 256 threads, col fixed per thread, 2 rows per iter
    {
        const int col   = tid & 127;
        const int n     = nbase + col;
        const int rloc0 = tid >> 7;
        if (n < K) {
            const float* sp = stage + rloc0 * STG_ROWW + col;
            int gr = m * 128 + rloc0;
            float* gp = logits + (size_t)gr * K + n;
            #pragma unroll 8
            for (int i = 0; i < 64; ++i) {
                if (gr < B) *gp = *sp;
                sp += 2 * STG_ROWW;
                gp += 2 * (size_t)K;
                gr += 2;
            }
        }
    }
    (void)dummy;
}

// ---------------------------------------------------------------------------
// launch 3: merge partials -> per-row loss, atomically accumulate mean
// ---------------------------------------------------------------------------
__global__ void lse_kernel(const float* __restrict__ logits,
                           const void* __restrict__ y_raw,
                           float* __restrict__ loss,
                           int B, int K, int P) {
    int b = blockIdx.x;
    if (b >= B) return;
    int tid = threadIdx.x;
    __shared__ float sm[256];
    const float4* part4 = (const float4*)(g_part + (size_t)b * P);
    const int P2 = P >> 1;

    float m = -1e30f;
    for (int i = tid; i < P2; i += 256) {
        float4 q = part4[i];
        m = fmaxf(m, fmaxf(q.x, q.z));
    }
    sm[tid] = m;
    __syncthreads();
    for (int k = 128; k > 0; k >>= 1) {
        if (tid < k) sm[tid] = fmaxf(sm[tid], sm[tid + k]);
        __syncthreads();
    }
    m = sm[0];
    __syncthreads();

    float s = 0.0f;
    for (int i = tid; i < P2; i += 256) {
        float4 q = part4[i];
        s += q.y * __expf(q.x - m) + q.w * __expf(q.z - m);
    }
    sm[tid] = s;
    __syncthreads();
    for (int k = 128; k > 0; k >>= 1) {
        if (tid < k) sm[tid] += sm[tid + k];
        __syncthreads();
    }
    if (tid == 0) {
        int yb = g_is64 ? (int)((const long long*)y_raw)[b]
                        : ((const int*)y_raw)[b];
        float lse = m + logf(sm[0]);
        atomicAdd(loss, (lse - logits[(size_t)b * K + yb]) / (float)B);
    }
}

// ---------------------------------------------------------------------------
// launch — inputs identified by element count
// ---------------------------------------------------------------------------
extern "C" void kernel_launch(void* const* d_in, const int* in_sizes, int n_in,
                              void* d_out, int out_size) {
    int order[16];
    for (int i = 0; i < n_in; ++i) order[i] = i;
    for (int i = 0; i < n_in; ++i)
        for (int j = i + 1; j < n_in; ++j)
            if (in_sizes[order[j]] > in_sizes[order[i]]) {
                int t = order[i]; order[i] = order[j]; order[j] = t;
            }
    const float* weights  = (const float*)d_in[order[0]];
    const void*  pi_p     = d_in[order[1]];
    const float* x        = (const float*)d_in[order[2]];
    const int*   path_len = (const int*)d_in[order[3]];
    const void*  y_p      = d_in[order[4]];

    const int pi_n = in_sizes[order[1]];
    const int K    = in_sizes[order[3]];
    const int B    = in_sizes[order[4]];
    const int Dmax = pi_n / K;

    const int ntiles = (K + 127) / 128;
    const int mtiles = (B + 127) / 128;
    const int Kpad   = ntiles * 128;
    const int Mpad   = mtiles * 128;
    const int P      = 2 * ntiles;

    float* out    = (float*)d_out;
    float* loss   = out;
    float* logits = out + 1;
    float* aw     = out + 1 + (size_t)B * K;

    cudaFuncSetAttribute(gemm_kernel, cudaFuncAttributeMaxDynamicSharedMemorySize, SMEM_TOTAL);

    detect_kernel<<<1, 32>>>((const unsigned int*)pi_p, loss);

    awx_kernel<<<Kpad + Mpad, 128>>>(weights, path_len, pi_p, x, aw, K, B, Dmax, Kpad);

    dim3 grid(ntiles, mtiles);
    gemm_kernel<<<grid, 256, SMEM_TOTAL>>>(logits, loss, B, K);

    lse_kernel<<<B, 256>>>(logits, y_p, loss, B, K, P);
}